// round 15
// baseline (speedup 1.0000x reference)
#include <cuda_runtime.h>
#include <cuda_bf16.h>
#include <math.h>
#include <stdint.h>

#define NN   20000
#define EE   320000
#define ET   340000   // EE + NN self loops
#define DINV 64
#define CCH  256
#define HCD  1024     // 4*256

// ---------------- scratch (device globals; no allocation in kernel_launch) ----
__device__ __align__(16) float g_h [NN * CCH];   // input-layer output (residual)
__device__ __align__(16) float g_xl[NN * HCD];
__device__ __align__(16) float g_xr[NN * HCD];
__device__ __align__(16) __nv_bfloat16 g_ahi[NN * HCD];
__device__ __align__(16) __nv_bfloat16 g_alo[NN * HCD];
__device__ __align__(16) __nv_bfloat16 g_whi[2 * HCD * HCD];  // combined [2048][1024] max
__device__ __align__(16) __nv_bfloat16 g_wlo[2 * HCD * HCD];
__device__ int g_deg[NN];
__device__ int g_off[NN + 1];
__device__ int g_cur[NN];
__device__ int g_csr[ET];    // stores RESOLVED source node id

// ---------------- CSR build ---------------------------------------------------
__global__ void k_zero_deg() {
    int i = blockIdx.x * blockDim.x + threadIdx.x;
    if (i < NN) g_deg[i] = 0;
}

__global__ void k_count(const int* __restrict__ dst) {
    int e = blockIdx.x * blockDim.x + threadIdx.x;
    if (e < ET) {
        int d = (e < EE) ? dst[e] : (e - EE);
        atomicAdd(&g_deg[d], 1);
    }
}

// single block, 1024 threads, chunk 20  (1024*20 >= 20000)
__global__ void k_scan() {
    __shared__ int sh[1024];
    const int CH = 20;
    int t = threadIdx.x;
    int loc[CH];
    int sum = 0;
#pragma unroll
    for (int j = 0; j < CH; ++j) {
        int i = t * CH + j;
        loc[j] = sum;
        if (i < NN) sum += g_deg[i];
    }
    sh[t] = sum;
    __syncthreads();
    for (int st = 1; st < 1024; st <<= 1) {
        int v = (t >= st) ? sh[t - st] : 0;
        __syncthreads();
        sh[t] += v;
        __syncthreads();
    }
    int base = (t > 0) ? sh[t - 1] : 0;
#pragma unroll
    for (int j = 0; j < CH; ++j) {
        int i = t * CH + j;
        if (i < NN) {
            int o = base + loc[j];
            g_off[i] = o;
            g_cur[i] = o;
        }
    }
    if (t == 1023) g_off[NN] = sh[1023];
}

__global__ void k_fill(const int* __restrict__ src, const int* __restrict__ dst) {
    int e = blockIdx.x * blockDim.x + threadIdx.x;
    if (e < ET) {
        int d, s;
        if (e < EE) { d = dst[e]; s = src[e]; }
        else        { d = e - EE; s = e - EE; }
        int pos = atomicAdd(&g_cur[d], 1);
        g_csr[pos] = s;
    }
}

// ---------------- weight split (smem-tiled transpose) --------------------------
__global__ void k_splitT(const float* __restrict__ W, __nv_bfloat16* __restrict__ hi,
                         __nv_bfloat16* __restrict__ lo, int K, int Nd, int rowoff) {
    __shared__ float sm[32][33];
    int tx = threadIdx.x & 31;
    int ty = threadIdx.x >> 5;          // 0..7
    int n0 = blockIdx.x * 32;
    int k0 = blockIdx.y * 32;
#pragma unroll
    for (int i = 0; i < 4; ++i) {
        int k = k0 + ty + i * 8;
        sm[ty + i * 8][tx] = W[(size_t)k * Nd + n0 + tx];
    }
    __syncthreads();
#pragma unroll
    for (int i = 0; i < 4; ++i) {
        int n = n0 + ty + i * 8;
        float v = sm[tx][ty + i * 8];
        __nv_bfloat16 hv = __float2bfloat16(v);
        size_t o = (size_t)(rowoff + n) * K + k0 + tx;
        hi[o] = hv;
        lo[o] = __float2bfloat16(v - __bfloat162float(hv));
    }
}

// ---------------- bf16x3 tensor-core GEMM, SW64 smem, 3-stage, 2 CTAs/SM ------
#define TILB   8192                     // 128 rows x 64 B (32 bf16), one tile
#define STAGEB (4 * TILB)               // Ahi,Alo,Bhi,Blo = 32 KB
#define NSTG_G 3
#define GEMM_SMEM (NSTG_G * STAGEB)     // 96 KB

#define SW64(off) ((off) ^ (((off) >> 3) & 0x30))

__device__ __forceinline__ void cp16g(uint32_t dstm, const void* srcm, int nbytes) {
    asm volatile("cp.async.cg.shared.global [%0], [%1], 16, %2;\n"
                 :: "r"(dstm), "l"(srcm), "r"(nbytes));
}

__device__ __forceinline__ void ldmx4(uint32_t* rg, uint32_t addr) {
    asm volatile("ldmatrix.sync.aligned.m8n8.x4.shared.b16 {%0,%1,%2,%3}, [%4];\n"
                 : "=r"(rg[0]), "=r"(rg[1]), "=r"(rg[2]), "=r"(rg[3]) : "r"(addr));
}

__device__ __forceinline__ void ldmx2(uint32_t* rg, uint32_t addr) {
    asm volatile("ldmatrix.sync.aligned.m8n8.x2.shared.b16 {%0,%1}, [%2];\n"
                 : "=r"(rg[0]), "=r"(rg[1]) : "r"(addr));
}

__device__ __forceinline__ void mma_bf16(float* cc, const uint32_t* aa, const uint32_t* bb) {
    asm volatile(
        "mma.sync.aligned.m16n8k16.row.col.f32.bf16.bf16.f32 "
        "{%0,%1,%2,%3}, {%4,%5,%6,%7}, {%8,%9}, {%0,%1,%2,%3};\n"
        : "+f"(cc[0]), "+f"(cc[1]), "+f"(cc[2]), "+f"(cc[3])
        : "r"(aa[0]), "r"(aa[1]), "r"(aa[2]), "r"(aa[3]), "r"(bb[0]), "r"(bb[1]));
}

#define ISSUE_TILE(ktv, bufv)                                                     \
    do {                                                                          \
        int k0q = (ktv) * 32;                                                     \
        uint32_t s0q = sb + (bufv) * STAGEB;                                      \
        for (int rrq = 0; rrq < 2; ++rrq) {                                       \
            int rq = lr + rrq * 64;                                               \
            uint32_t boffq = (uint32_t)(rq * 64 + lc * 2);                        \
            uint32_t swq = SW64(boffq);                                           \
            int growq = row0 + rq;                                                \
            int okq = (growq < M) ? 16 : 0;                                       \
            int crq = (growq < M) ? growq : 0;                                    \
            size_t gaq = (size_t)crq * K + k0q + lc;                              \
            cp16g(s0q + swq, Ahi + gaq, okq);                                     \
            cp16g(s0q + TILB + swq, Alo + gaq, okq);                              \
            size_t gbq = (size_t)(col0 + rq) * K + k0q + lc;                      \
            cp16g(s0q + 2 * TILB + swq, Bhi + gbq, 16);                           \
            cp16g(s0q + 3 * TILB + swq, Blo + gbq, 16);                           \
        }                                                                         \
        asm volatile("cp.async.commit_group;\n" ::: "memory");                    \
    } while (0)

__global__ __launch_bounds__(256, 2) void gemm_b3(
    const __nv_bfloat16* __restrict__ Ahi, const __nv_bfloat16* __restrict__ Alo,
    const __nv_bfloat16* __restrict__ Bhi, const __nv_bfloat16* __restrict__ Blo,
    const float* __restrict__ biasL, const float* __restrict__ biasR,
    float* __restrict__ Cl, float* __restrict__ Cr,
    int M, int Nl, int NdOut, int K) {
    extern __shared__ char smem[];
    const uint32_t sb = (uint32_t)__cvta_generic_to_shared(smem);

    const int tid  = threadIdx.x;
    const int warp = tid >> 5;
    const int lane = tid & 31;
    const int row0 = blockIdx.y * 128;
    const int col0 = blockIdx.x * 128;   // row in combined weight matrix
    const int wm = (warp >> 2) * 64;
    const int wn = (warp & 3) * 32;

    const int lr = tid >> 2;
    const int lc = (tid & 3) * 8;

    float    acc[4][4][4];
    uint32_t fAh[4][4], fAl[4][4], fBh[4][2], fBl[4][2];

#pragma unroll
    for (int mi = 0; mi < 4; ++mi)
#pragma unroll
        for (int ni = 0; ni < 4; ++ni)
#pragma unroll
            for (int rr = 0; rr < 4; ++rr) acc[mi][ni][rr] = 0.f;

    const int nk = K / 32;

    ISSUE_TILE(0, 0);
    if (nk > 1) ISSUE_TILE(1, 1);

    for (int kt = 0; kt < nk; ++kt) {
        if (kt + 1 < nk) asm volatile("cp.async.wait_group 1;\n" ::: "memory");
        else             asm volatile("cp.async.wait_group 0;\n" ::: "memory");
        __syncthreads();
        if (kt + 2 < nk) ISSUE_TILE(kt + 2, (kt + 2) % NSTG_G);

        const int buf = kt % NSTG_G;
        const uint32_t sA  = sb + buf * STAGEB;
        const uint32_t sBB = sA + 2 * TILB;

#pragma unroll
        for (int kk = 0; kk < 32; kk += 16) {
#pragma unroll
            for (int mi = 0; mi < 4; ++mi) {
                uint32_t aoff = (uint32_t)((wm + mi * 16 + (lane & 15)) * 64 +
                                           (kk + (lane >> 4) * 8) * 2);
                uint32_t aswz = SW64(aoff);
                ldmx4(fAh[mi], sA + aswz);
                ldmx4(fAl[mi], sA + TILB + aswz);
            }
#pragma unroll
            for (int ni = 0; ni < 4; ++ni) {
                uint32_t boff = (uint32_t)((wn + ni * 8 + (lane & 7)) * 64 +
                                           (kk + ((lane >> 3) & 1) * 8) * 2);
                uint32_t bswz = SW64(boff);
                ldmx2(fBh[ni], sBB + bswz);
                ldmx2(fBl[ni], sBB + TILB + bswz);
            }
#pragma unroll
            for (int mi = 0; mi < 4; ++mi)
#pragma unroll
                for (int ni = 0; ni < 4; ++ni) {
                    mma_bf16(acc[mi][ni], fAh[mi], fBh[ni]);
                    mma_bf16(acc[mi][ni], fAh[mi], fBl[ni]);
                    mma_bf16(acc[mi][ni], fAl[mi], fBh[ni]);
                }
        }
    }

    // ---- epilogue: route columns to Cl or Cr ----
    const float* bias = (col0 < Nl) ? biasL : biasR;
    float* C          = (col0 < Nl) ? Cl : Cr;
    const int cc0     = (col0 < Nl) ? col0 : col0 - Nl;

#pragma unroll
    for (int mi = 0; mi < 4; ++mi)
#pragma unroll
        for (int ni = 0; ni < 4; ++ni) {
            int c = cc0 + wn + ni * 8 + (lane & 3) * 2;
            float b0 = bias[c], b1 = bias[c + 1];
            int r0 = row0 + wm + mi * 16 + (lane >> 2);
            if (r0 < M) {
                float2 v = make_float2(acc[mi][ni][0] + b0, acc[mi][ni][1] + b1);
                *(float2*)(C + (size_t)r0 * NdOut + c) = v;
            }
            int r1 = r0 + 8;
            if (r1 < M) {
                float2 v = make_float2(acc[mi][ni][2] + b0, acc[mi][ni][3] + b1);
                *(float2*)(C + (size_t)r1 * NdOut + c) = v;
            }
        }
}

// ---------------- fp32 SGEMM (input layer, + split epilogue) ------------------
__global__ void sgemm_in(const float* __restrict__ A, const float* __restrict__ B,
                         const float* __restrict__ bias, float* __restrict__ Cout,
                         __nv_bfloat16* __restrict__ ohi, __nv_bfloat16* __restrict__ olo,
                         int M, int Nd, int K) {
    __shared__ float As[8][128];
    __shared__ float Bs[8][128];
    int tid  = threadIdx.x;
    int row0 = blockIdx.y * 128;
    int col0 = blockIdx.x * 128;
    int tx = tid & 15;
    int ty = tid >> 4;
    int arow = tid >> 1;
    int akq  = (tid & 1) * 4;
    int brow = tid >> 5;
    int bcol = (tid & 31) * 4;

    float acc[8][8];
#pragma unroll
    for (int i = 0; i < 8; ++i)
#pragma unroll
        for (int j = 0; j < 8; ++j) acc[i][j] = 0.f;

    for (int k0 = 0; k0 < K; k0 += 8) {
        float4 av = make_float4(0.f, 0.f, 0.f, 0.f);
        if (row0 + arow < M)
            av = *(const float4*)(A + (size_t)(row0 + arow) * K + k0 + akq);
        As[akq + 0][arow] = av.x;
        As[akq + 1][arow] = av.y;
        As[akq + 2][arow] = av.z;
        As[akq + 3][arow] = av.w;
        float4 bv = *(const float4*)(B + (size_t)(k0 + brow) * Nd + col0 + bcol);
        *(float4*)&Bs[brow][bcol] = bv;
        __syncthreads();
#pragma unroll
        for (int k = 0; k < 8; ++k) {
            float4 a0 = *(float4*)&As[k][ty * 8];
            float4 a1 = *(float4*)&As[k][ty * 8 + 4];
            float4 b0 = *(float4*)&Bs[k][tx * 8];
            float4 b1 = *(float4*)&Bs[k][tx * 8 + 4];
            float ar[8] = {a0.x, a0.y, a0.z, a0.w, a1.x, a1.y, a1.z, a1.w};
            float br[8] = {b0.x, b0.y, b0.z, b0.w, b1.x, b1.y, b1.z, b1.w};
#pragma unroll
            for (int i = 0; i < 8; ++i)
#pragma unroll
                for (int j = 0; j < 8; ++j)
                    acc[i][j] = fmaf(ar[i], br[j], acc[i][j]);
        }
        __syncthreads();
    }

    float bb[8];
#pragma unroll
    for (int j = 0; j < 8; ++j) bb[j] = bias[col0 + tx * 8 + j];

#pragma unroll
    for (int i = 0; i < 8; ++i) {
        int r = row0 + ty * 8 + i;
        if (r < M) {
            size_t ob = (size_t)r * Nd + col0 + tx * 8;
            float v[8];
#pragma unroll
            for (int j = 0; j < 8; ++j) {
                float t = acc[i][j] + bb[j];
                t = (t > 0.f) ? t : 0.01f * t;
                v[j] = t;
                __nv_bfloat16 hv = __float2bfloat16(t);
                ohi[ob + j] = hv;
                olo[ob + j] = __float2bfloat16(t - __bfloat162float(hv));
            }
            *(float4*)(Cout + ob)     = make_float4(v[0], v[1], v[2], v[3]);
            *(float4*)(Cout + ob + 4) = make_float4(v[4], v[5], v[6], v[7]);
        }
    }
}

// ---------------- helpers for agg ---------------------------------------------
__device__ __forceinline__ void ld8(float* d, const float* p) {
    float4 a = *(const float4*)p;
    float4 b = *(const float4*)(p + 4);
    d[0]=a.x; d[1]=a.y; d[2]=a.z; d[3]=a.w;
    d[4]=b.x; d[5]=b.y; d[6]=b.z; d[7]=b.w;
}

// ---------------- GATv2 agg, warp-per-head (H=4), edge-pair ILP ---------------
__global__ __launch_bounds__(128) void gat_agg_w(
    const float* __restrict__ xl, const float* __restrict__ xr,
    const float* __restrict__ att, const float* __restrict__ bias,
    __nv_bfloat16* __restrict__ ohi, __nv_bfloat16* __restrict__ olo) {
    int node = blockIdx.x;
    int w    = threadIdx.x >> 5;
    int lane = threadIdx.x & 31;
    int cof  = w * CCH + lane * 8;               // channel offset in [H*C]
    size_t ib = (size_t)node * HCD + cof;

    float attv[8], xrv[8], acc[8];
#pragma unroll
    for (int j = 0; j < 8; ++j) { attv[j] = att[cof + j]; acc[j] = 0.f; }
    ld8(xrv, xr + ib);

    int pbeg = g_off[node], pend = g_off[node + 1];
    float m = -INFINITY, den = 0.f;

    float cur0[8], cur1[8];
    ld8(cur0, xl + (size_t)g_csr[pbeg] * HCD + cof);
    if (pbeg + 1 < pend)
        ld8(cur1, xl + (size_t)g_csr[pbeg + 1] * HCD + cof);

    int p = pbeg;
    while (p + 1 < pend) {
        float nxt0[8], nxt1[8];
        bool n0 = (p + 2 < pend), n1 = (p + 3 < pend);
        if (n0) ld8(nxt0, xl + (size_t)g_csr[p + 2] * HCD + cof);
        if (n1) ld8(nxt1, xl + (size_t)g_csr[p + 3] * HCD + cof);
        float p0 = 0.f, p1 = 0.f;
#pragma unroll
        for (int j = 0; j < 8; ++j) {
            float t0 = cur0[j] + xrv[j];
            t0 = (t0 > 0.f) ? t0 : 0.2f * t0;
            p0 = fmaf(attv[j], t0, p0);
            float t1 = cur1[j] + xrv[j];
            t1 = (t1 > 0.f) ? t1 : 0.2f * t1;
            p1 = fmaf(attv[j], t1, p1);
        }
#pragma unroll
        for (int o = 16; o > 0; o >>= 1) {
            p0 += __shfl_xor_sync(0xffffffffu, p0, o);
            p1 += __shfl_xor_sync(0xffffffffu, p1, o);
        }
        float nm = fmaxf(m, fmaxf(p0, p1));
        float sc = __expf(m - nm);
        float e0 = __expf(p0 - nm);
        float e1 = __expf(p1 - nm);
        den = den * sc + e0 + e1;
#pragma unroll
        for (int j = 0; j < 8; ++j)
            acc[j] = fmaf(acc[j], sc, fmaf(e0, cur0[j], e1 * cur1[j]));
        m = nm;
        if (n0) {
#pragma unroll
            for (int j = 0; j < 8; ++j) cur0[j] = nxt0[j];
        }
        if (n1) {
#pragma unroll
            for (int j = 0; j < 8; ++j) cur1[j] = nxt1[j];
        }
        p += 2;
    }
    if (p < pend) {       // odd tail (cur0 holds edge p)
        float p0 = 0.f;
#pragma unroll
        for (int j = 0; j < 8; ++j) {
            float t0 = cur0[j] + xrv[j];
            t0 = (t0 > 0.f) ? t0 : 0.2f * t0;
            p0 = fmaf(attv[j], t0, p0);
        }
#pragma unroll
        for (int o = 16; o > 0; o >>= 1)
            p0 += __shfl_xor_sync(0xffffffffu, p0, o);
        float nm = fmaxf(m, p0);
        float sc = __expf(m - nm);
        float e0 = __expf(p0 - nm);
        den = den * sc + e0;
#pragma unroll
        for (int j = 0; j < 8; ++j) acc[j] = fmaf(acc[j], sc, e0 * cur0[j]);
    }

    float inv = 1.f / den;
#pragma unroll
    for (int j = 0; j < 8; ++j) {
        float v = acc[j] * inv + bias[cof + j];
        v = (v > 0.f) ? v : expm1f(v);           // elu
        __nv_bfloat16 hv = __float2bfloat16(v);
        ohi[ib + j] = hv;
        olo[ib + j] = __float2bfloat16(v - __bfloat162float(hv));
    }
}

// ---------------- conv3 agg (H=1) fused with output layer ---------------------
__global__ __launch_bounds__(256) void gat_final(
    const float* __restrict__ xl, const float* __restrict__ xr,
    const float* __restrict__ att, const float* __restrict__ bias,
    const float* __restrict__ Wout, const float* __restrict__ bout,
    float* __restrict__ outp) {
    int node = blockIdx.x * 8 + (threadIdx.x >> 5);
    if (node >= NN) return;
    int lane = threadIdx.x & 31;
    int cof  = lane * 8;
    size_t ib = (size_t)node * CCH + cof;

    float attv[8], xrv[8], acc[8];
#pragma unroll
    for (int j = 0; j < 8; ++j) { attv[j] = att[cof + j]; acc[j] = 0.f; }
    ld8(xrv, xr + ib);

    int pbeg = g_off[node], pend = g_off[node + 1];
    float m = -INFINITY, den = 0.f;

    float cur0[8], cur1[8];
    ld8(cur0, xl + (size_t)g_csr[pbeg] * CCH + cof);
    if (pbeg + 1 < pend)
        ld8(cur1, xl + (size_t)g_csr[pbeg + 1] * CCH + cof);

    int p = pbeg;
    while (p + 1 < pend) {
        float nxt0[8], nxt1[8];
        bool n0 = (p + 2 < pend), n1 = (p + 3 < pend);
        if (n0) ld8(nxt0, xl + (size_t)g_csr[p + 2] * CCH + cof);
        if (n1) ld8(nxt1, xl + (size_t)g_csr[p + 3] * CCH + cof);
        float p0 = 0.f, p1 = 0.f;
#pragma unroll
        for (int j = 0; j < 8; ++j) {
            float t0 = cur0[j] + xrv[j];
            t0 = (t0 > 0.f) ? t0 : 0.2f * t0;
            p0 = fmaf(attv[j], t0, p0);
            float t1 = cur1[j] + xrv[j];
            t1 = (t1 > 0.f) ? t1 : 0.2f * t1;
            p1 = fmaf(attv[j], t1, p1);
        }
#pragma unroll
        for (int o = 16; o > 0; o >>= 1) {
            p0 += __shfl_xor_sync(0xffffffffu, p0, o);
            p1 += __shfl_xor_sync(0xffffffffu, p1, o);
        }
        float nm = fmaxf(m, fmaxf(p0, p1));
        float sc = __expf(m - nm);
        float e0 = __expf(p0 - nm);
        float e1 = __expf(p1 - nm);
        den = den * sc + e0 + e1;
#pragma unroll
        for (int j = 0; j < 8; ++j)
            acc[j] = fmaf(acc[j], sc, fmaf(e0, cur0[j], e1 * cur1[j]));
        m = nm;
        if (n0) {
#pragma unroll
            for (int j = 0; j < 8; ++j) cur0[j] = nxt0[j];
        }
        if (n1) {
#pragma unroll
            for (int j = 0; j < 8; ++j) cur1[j] = nxt1[j];
        }
        p += 2;
    }
    if (p < pend) {
        float p0 = 0.f;
#pragma unroll
        for (int j = 0; j < 8; ++j) {
            float t0 = cur0[j] + xrv[j];
            t0 = (t0 > 0.f) ? t0 : 0.2f * t0;
            p0 = fmaf(attv[j], t0, p0);
        }
#pragma unroll
        for (int o = 16; o > 0; o >>= 1)
            p0 += __shfl_xor_sync(0xffffffffu, p0, o);
        float nm = fmaxf(m, p0);
        float sc = __expf(m - nm);
        float e0 = __expf(p0 - nm);
        den = den * sc + e0;
#pragma unroll
        for (int j = 0; j < 8; ++j) acc[j] = fmaf(acc[j], sc, e0 * cur0[j]);
    }

    float inv = 1.f / den;
    float sum = 0.f;
#pragma unroll
    for (int j = 0; j < 8; ++j) {
        float v = acc[j] * inv + bias[cof + j];
        v = (v > 0.f) ? v : 0.01f * v;           // leaky
        v += g_h[ib + j];                        // residual
        sum = fmaf(v, Wout[cof + j], sum);
    }
#pragma unroll
    for (int o = 16; o > 0; o >>= 1)
        sum += __shfl_xor_sync(0xffffffffu, sum, o);
    if (lane == 0) outp[node] = sum + bout[0];
}

// ---------------- launch ------------------------------------------------------
extern "C" void kernel_launch(void* const* d_in, const int* in_sizes, int n_in,
                              void* d_out, int out_size) {
    const float* x    = (const float*)d_in[0];
    const int*   src  = (const int*)  d_in[1];
    const int*   dst  = (const int*)  d_in[2];
    const float* W_in = (const float*)d_in[3];
    const float* b_in = (const float*)d_in[4];
    const float* Wl1  = (const float*)d_in[5];
    const float* bl1  = (const float*)d_in[6];
    const float* Wr1  = (const float*)d_in[7];
    const float* br1  = (const float*)d_in[8];
    const float* att1 = (const float*)d_in[9];
    const float* bias1= (const float*)d_in[10];
    const float* Wl2  = (const float*)d_in[11];
    const float* bl2  = (const float*)d_in[12];
    const float* Wr2  = (const float*)d_in[13];
    const float* br2  = (const float*)d_in[14];
    const float* att2 = (const float*)d_in[15];
    const float* bias2= (const float*)d_in[16];
    const float* Wl3  = (const float*)d_in[17];
    const float* bl3  = (const float*)d_in[18];
    const float* Wr3  = (const float*)d_in[19];
    const float* br3  = (const float*)d_in[20];
    const float* att3 = (const float*)d_in[21];
    const float* bias3= (const float*)d_in[22];
    const float* Wout = (const float*)d_in[23];
    const float* bout = (const float*)d_in[24];
    float* outp = (float*)d_out;

    float *h, *xl, *xr;
    __nv_bfloat16 *ahi, *alo, *whi, *wlo;
    cudaGetSymbolAddress((void**)&h,  g_h);
    cudaGetSymbolAddress((void**)&xl, g_xl);
    cudaGetSymbolAddress((void**)&xr, g_xr);
    cudaGetSymbolAddress((void**)&ahi, g_ahi);
    cudaGetSymbolAddress((void**)&alo, g_alo);
    cudaGetSymbolAddress((void**)&whi, g_whi);
    cudaGetSymbolAddress((void**)&wlo, g_wlo);

    cudaFuncSetAttribute(gemm_b3, cudaFuncAttributeMaxDynamicSharedMemorySize, GEMM_SMEM);

    // CSR build (order by dst, store resolved src)
    k_zero_deg<<<(NN + 255) / 256, 256>>>();
    k_count<<<(ET + 255) / 256, 256>>>(dst);
    k_scan<<<1, 1024>>>();
    k_fill<<<(ET + 255) / 256, 256>>>(src, dst);

    dim3 blk(256);
    int mgrid = (NN + 127) / 128;

    // input layer: h = leaky(x @ W_in + b_in), plus bf16 hi/lo for conv1
    sgemm_in<<<dim3(2, mgrid), blk>>>(x, W_in, b_in, h, ahi, alo, NN, 256, DINV);

    // ---- conv1: K=256, combined N=2048 ----
    k_splitT<<<dim3(1024 / 32, 256 / 32), blk>>>(Wl1, whi, wlo, 256, 1024, 0);
    k_splitT<<<dim3(1024 / 32, 256 / 32), blk>>>(Wr1, whi, wlo, 256, 1024, 1024);
    gemm_b3<<<dim3(16, mgrid), blk, GEMM_SMEM>>>(ahi, alo, whi, wlo, bl1, br1,
                                                 xl, xr, NN, 1024, 1024, 256);
    gat_agg_w<<<NN, 128>>>(xl, xr, att1, bias1, ahi, alo);

    // ---- conv2: K=1024, combined N=2048 ----
    k_splitT<<<dim3(1024 / 32, 1024 / 32), blk>>>(Wl2, whi, wlo, 1024, 1024, 0);
    k_splitT<<<dim3(1024 / 32, 1024 / 32), blk>>>(Wr2, whi, wlo, 1024, 1024, 1024);
    gemm_b3<<<dim3(16, mgrid), blk, GEMM_SMEM>>>(ahi, alo, whi, wlo, bl2, br2,
                                                 xl, xr, NN, 1024, 1024, 1024);
    gat_agg_w<<<NN, 128>>>(xl, xr, att2, bias2, ahi, alo);

    // ---- conv3: K=1024, combined N=512 (heads=1, no concat) + output layer ----
    k_splitT<<<dim3(256 / 32, 1024 / 32), blk>>>(Wl3, whi, wlo, 1024, 256, 0);
    k_splitT<<<dim3(256 / 32, 1024 / 32), blk>>>(Wr3, whi, wlo, 1024, 256, 256);
    gemm_b3<<<dim3(4, mgrid), blk, GEMM_SMEM>>>(ahi, alo, whi, wlo, bl3, br3,
                                                xl, xr, NN, 256, 256, 1024);
    gat_final<<<(NN + 7) / 8, 256>>>(xl, xr, att3, bias3, Wout, bout, outp);
}

// round 16
// speedup vs baseline: 1.4472x; 1.4472x over previous
#include <cuda_runtime.h>
#include <cuda_bf16.h>
#include <math.h>
#include <stdint.h>

#define NN   20000
#define EE   320000
#define ET   340000   // EE + NN self loops
#define DINV 64
#define CCH  256
#define HCD  1024     // 4*256

// ---------------- scratch (device globals; no allocation in kernel_launch) ----
__device__ __align__(16) float g_h [NN * CCH];   // input-layer output (residual)
__device__ __align__(16) float g_xl[NN * HCD];
__device__ __align__(16) float g_xr[NN * HCD];
__device__ __align__(16) __nv_bfloat16 g_ahi[NN * HCD];
__device__ __align__(16) __nv_bfloat16 g_alo[NN * HCD];
__device__ __align__(16) __nv_bfloat16 g_w1hi[2048 * 256];
__device__ __align__(16) __nv_bfloat16 g_w1lo[2048 * 256];
__device__ __align__(16) __nv_bfloat16 g_w2hi[2048 * 1024];
__device__ __align__(16) __nv_bfloat16 g_w2lo[2048 * 1024];
__device__ __align__(16) __nv_bfloat16 g_w3hi[512 * 1024];
__device__ __align__(16) __nv_bfloat16 g_w3lo[512 * 1024];
__device__ int g_deg[NN];
__device__ int g_off[NN + 1];
__device__ int g_cur[NN];
__device__ int g_csr[ET];    // stores RESOLVED source node id

// ---------------- CSR build ---------------------------------------------------
__global__ void k_zero_deg() {
    int i = blockIdx.x * blockDim.x + threadIdx.x;
    if (i < NN) g_deg[i] = 0;
}

__global__ void k_count(const int* __restrict__ dst) {
    int e = blockIdx.x * blockDim.x + threadIdx.x;
    if (e < ET) {
        int d = (e < EE) ? dst[e] : (e - EE);
        atomicAdd(&g_deg[d], 1);
    }
}

// single block, 1024 threads, chunk 20  (1024*20 >= 20000)
__global__ void k_scan() {
    __shared__ int sh[1024];
    const int CH = 20;
    int t = threadIdx.x;
    int loc[CH];
    int sum = 0;
#pragma unroll
    for (int j = 0; j < CH; ++j) {
        int i = t * CH + j;
        loc[j] = sum;
        if (i < NN) sum += g_deg[i];
    }
    sh[t] = sum;
    __syncthreads();
    for (int st = 1; st < 1024; st <<= 1) {
        int v = (t >= st) ? sh[t - st] : 0;
        __syncthreads();
        sh[t] += v;
        __syncthreads();
    }
    int base = (t > 0) ? sh[t - 1] : 0;
#pragma unroll
    for (int j = 0; j < CH; ++j) {
        int i = t * CH + j;
        if (i < NN) {
            int o = base + loc[j];
            g_off[i] = o;
            g_cur[i] = o;
        }
    }
    if (t == 1023) g_off[NN] = sh[1023];
}

__global__ void k_fill(const int* __restrict__ src, const int* __restrict__ dst) {
    int e = blockIdx.x * blockDim.x + threadIdx.x;
    if (e < ET) {
        int d, s;
        if (e < EE) { d = dst[e]; s = src[e]; }
        else        { d = e - EE; s = e - EE; }
        int pos = atomicAdd(&g_cur[d], 1);
        g_csr[pos] = s;
    }
}

// ---------------- weight split (smem-tiled transpose) --------------------------
__global__ void k_splitT(const float* __restrict__ W, __nv_bfloat16* __restrict__ hi,
                         __nv_bfloat16* __restrict__ lo, int K, int Nd, int rowoff) {
    __shared__ float sm[32][33];
    int tx = threadIdx.x & 31;
    int ty = threadIdx.x >> 5;          // 0..7
    int n0 = blockIdx.x * 32;
    int k0 = blockIdx.y * 32;
#pragma unroll
    for (int i = 0; i < 4; ++i) {
        int k = k0 + ty + i * 8;
        sm[ty + i * 8][tx] = W[(size_t)k * Nd + n0 + tx];
    }
    __syncthreads();
#pragma unroll
    for (int i = 0; i < 4; ++i) {
        int n = n0 + ty + i * 8;
        float v = sm[tx][ty + i * 8];
        __nv_bfloat16 hv = __float2bfloat16(v);
        size_t o = (size_t)(rowoff + n) * K + k0 + tx;
        hi[o] = hv;
        lo[o] = __float2bfloat16(v - __bfloat162float(hv));
    }
}

// ---------------- bf16x3 tensor-core GEMM (R14-proven: 128x128, 2 CTAs/SM) ----
#define LDS_T  40                       // padded smem row (bf16 elems)
#define TSZB   (128 * LDS_T * 2)        // one tile, bytes
#define STAGEB (4 * TSZB)               // Ahi,Alo,Bhi,Blo
#define GEMM_SMEM (2 * STAGEB)

__device__ __forceinline__ void cp16g(uint32_t dstm, const void* srcm, int nbytes) {
    asm volatile("cp.async.cg.shared.global [%0], [%1], 16, %2;\n"
                 :: "r"(dstm), "l"(srcm), "r"(nbytes));
}

__device__ __forceinline__ void ldmx4(uint32_t* rg, uint32_t addr) {
    asm volatile("ldmatrix.sync.aligned.m8n8.x4.shared.b16 {%0,%1,%2,%3}, [%4];\n"
                 : "=r"(rg[0]), "=r"(rg[1]), "=r"(rg[2]), "=r"(rg[3]) : "r"(addr));
}

__device__ __forceinline__ void ldmx2(uint32_t* rg, uint32_t addr) {
    asm volatile("ldmatrix.sync.aligned.m8n8.x2.shared.b16 {%0,%1}, [%2];\n"
                 : "=r"(rg[0]), "=r"(rg[1]) : "r"(addr));
}

__device__ __forceinline__ void mma_bf16(float* cc, const uint32_t* aa, const uint32_t* bb) {
    asm volatile(
        "mma.sync.aligned.m16n8k16.row.col.f32.bf16.bf16.f32 "
        "{%0,%1,%2,%3}, {%4,%5,%6,%7}, {%8,%9}, {%0,%1,%2,%3};\n"
        : "+f"(cc[0]), "+f"(cc[1]), "+f"(cc[2]), "+f"(cc[3])
        : "r"(aa[0]), "r"(aa[1]), "r"(aa[2]), "r"(aa[3]), "r"(bb[0]), "r"(bb[1]));
}

#define ISSUE_TILE(ktv, bufv)                                                     \
    do {                                                                          \
        int k0q = (ktv) * 32;                                                     \
        uint32_t s0q = sb + (bufv) * STAGEB;                                      \
        for (int rrq = 0; rrq < 2; ++rrq) {                                       \
            int rq = lr + rrq * 64;                                               \
            int growq = row0 + rq;                                                \
            int okq = (growq < M) ? 16 : 0;                                       \
            int crq = (growq < M) ? growq : 0;                                    \
            size_t gaq = (size_t)crq * K + k0q + lc;                              \
            uint32_t daq = s0q + (uint32_t)(rq * LDS_T + lc) * 2;                 \
            cp16g(daq, Ahi + gaq, okq);                                           \
            cp16g(daq + TSZB, Alo + gaq, okq);                                    \
            size_t gbq = (size_t)(col0 + rq) * K + k0q + lc;                      \
            uint32_t dbq = s0q + 2 * TSZB + (uint32_t)(rq * LDS_T + lc) * 2;      \
            cp16g(dbq, Bhi + gbq, 16);                                            \
            cp16g(dbq + TSZB, Blo + gbq, 16);                                     \
        }                                                                         \
        asm volatile("cp.async.commit_group;\n" ::: "memory");                    \
    } while (0)

__global__ __launch_bounds__(256, 2) void gemm_b3(
    const __nv_bfloat16* __restrict__ Ahi, const __nv_bfloat16* __restrict__ Alo,
    const __nv_bfloat16* __restrict__ Bhi, const __nv_bfloat16* __restrict__ Blo,
    const float* __restrict__ biasL, const float* __restrict__ biasR,
    float* __restrict__ Cl, float* __restrict__ Cr,
    int M, int Nl, int NdOut, int K) {
    extern __shared__ char smem[];
    const uint32_t sb = (uint32_t)__cvta_generic_to_shared(smem);

    const int tid  = threadIdx.x;
    const int warp = tid >> 5;
    const int lane = tid & 31;
    const int row0 = blockIdx.y * 128;
    const int col0 = blockIdx.x * 128;   // row in combined weight matrix
    const int wm = (warp >> 2) * 64;
    const int wn = (warp & 3) * 32;

    const int lr = tid >> 2;
    const int lc = (tid & 3) * 8;

    float    acc[4][4][4];
    uint32_t fAh[4][4], fAl[4][4], fBh[4][2], fBl[4][2];

#pragma unroll
    for (int mi = 0; mi < 4; ++mi)
#pragma unroll
        for (int ni = 0; ni < 4; ++ni)
#pragma unroll
            for (int rr = 0; rr < 4; ++rr) acc[mi][ni][rr] = 0.f;

    const int nk = K / 32;

    ISSUE_TILE(0, 0);

    for (int kt = 0; kt < nk; ++kt) {
        const int buf = kt & 1;
        if (kt + 1 < nk) {
            ISSUE_TILE(kt + 1, buf ^ 1);
            asm volatile("cp.async.wait_group 1;\n" ::: "memory");
        } else {
            asm volatile("cp.async.wait_group 0;\n" ::: "memory");
        }
        __syncthreads();

        const uint32_t sA  = sb + buf * STAGEB;
        const uint32_t sBB = sA + 2 * TSZB;

#pragma unroll
        for (int kk = 0; kk < 32; kk += 16) {
            const uint32_t baseA = sA +
                (uint32_t)((wm + (lane & 15)) * LDS_T + kk + (lane >> 4) * 8) * 2;
            const uint32_t baseB = sBB +
                (uint32_t)((wn + (lane & 7)) * LDS_T + kk + ((lane >> 3) & 1) * 8) * 2;

#pragma unroll
            for (int mi = 0; mi < 4; ++mi) {
                uint32_t ad = baseA + (uint32_t)(mi * 16 * LDS_T) * 2;
                ldmx4(fAh[mi], ad);
                ldmx4(fAl[mi], ad + TSZB);
            }
#pragma unroll
            for (int ni = 0; ni < 4; ++ni) {
                uint32_t bdadr = baseB + (uint32_t)(ni * 8 * LDS_T) * 2;
                ldmx2(fBh[ni], bdadr);
                ldmx2(fBl[ni], bdadr + TSZB);
            }
#pragma unroll
            for (int mi = 0; mi < 4; ++mi)
#pragma unroll
                for (int ni = 0; ni < 4; ++ni) {
                    mma_bf16(acc[mi][ni], fAh[mi], fBh[ni]);
                    mma_bf16(acc[mi][ni], fAh[mi], fBl[ni]);
                    mma_bf16(acc[mi][ni], fAl[mi], fBh[ni]);
                }
        }
        __syncthreads();
    }

    // ---- epilogue: route columns to Cl or Cr ----
    const float* bias = (col0 < Nl) ? biasL : biasR;
    float* C          = (col0 < Nl) ? Cl : Cr;
    const int cc0     = (col0 < Nl) ? col0 : col0 - Nl;

#pragma unroll
    for (int mi = 0; mi < 4; ++mi)
#pragma unroll
        for (int ni = 0; ni < 4; ++ni) {
            int c = cc0 + wn + ni * 8 + (lane & 3) * 2;
            float b0 = bias[c], b1 = bias[c + 1];
            int r0 = row0 + wm + mi * 16 + (lane >> 2);
            if (r0 < M) {
                float2 v = make_float2(acc[mi][ni][0] + b0, acc[mi][ni][1] + b1);
                *(float2*)(C + (size_t)r0 * NdOut + c) = v;
            }
            int r1 = r0 + 8;
            if (r1 < M) {
                float2 v = make_float2(acc[mi][ni][2] + b0, acc[mi][ni][3] + b1);
                *(float2*)(C + (size_t)r1 * NdOut + c) = v;
            }
        }
}

// ---------------- fp32 SGEMM (input layer, + split epilogue) ------------------
__global__ void sgemm_in(const float* __restrict__ A, const float* __restrict__ B,
                         const float* __restrict__ bias, float* __restrict__ Cout,
                         __nv_bfloat16* __restrict__ ohi, __nv_bfloat16* __restrict__ olo,
                         int M, int Nd, int K) {
    __shared__ float As[8][128];
    __shared__ float Bs[8][128];
    int tid  = threadIdx.x;
    int row0 = blockIdx.y * 128;
    int col0 = blockIdx.x * 128;
    int tx = tid & 15;
    int ty = tid >> 4;
    int arow = tid >> 1;
    int akq  = (tid & 1) * 4;
    int brow = tid >> 5;
    int bcol = (tid & 31) * 4;

    float acc[8][8];
#pragma unroll
    for (int i = 0; i < 8; ++i)
#pragma unroll
        for (int j = 0; j < 8; ++j) acc[i][j] = 0.f;

    for (int k0 = 0; k0 < K; k0 += 8) {
        float4 av = make_float4(0.f, 0.f, 0.f, 0.f);
        if (row0 + arow < M)
            av = *(const float4*)(A + (size_t)(row0 + arow) * K + k0 + akq);
        As[akq + 0][arow] = av.x;
        As[akq + 1][arow] = av.y;
        As[akq + 2][arow] = av.z;
        As[akq + 3][arow] = av.w;
        float4 bv = *(const float4*)(B + (size_t)(k0 + brow) * Nd + col0 + bcol);
        *(float4*)&Bs[brow][bcol] = bv;
        __syncthreads();
#pragma unroll
        for (int k = 0; k < 8; ++k) {
            float4 a0 = *(float4*)&As[k][ty * 8];
            float4 a1 = *(float4*)&As[k][ty * 8 + 4];
            float4 b0 = *(float4*)&Bs[k][tx * 8];
            float4 b1 = *(float4*)&Bs[k][tx * 8 + 4];
            float ar[8] = {a0.x, a0.y, a0.z, a0.w, a1.x, a1.y, a1.z, a1.w};
            float br[8] = {b0.x, b0.y, b0.z, b0.w, b1.x, b1.y, b1.z, b1.w};
#pragma unroll
            for (int i = 0; i < 8; ++i)
#pragma unroll
                for (int j = 0; j < 8; ++j)
                    acc[i][j] = fmaf(ar[i], br[j], acc[i][j]);
        }
        __syncthreads();
    }

    float bb[8];
#pragma unroll
    for (int j = 0; j < 8; ++j) bb[j] = bias[col0 + tx * 8 + j];

#pragma unroll
    for (int i = 0; i < 8; ++i) {
        int r = row0 + ty * 8 + i;
        if (r < M) {
            size_t ob = (size_t)r * Nd + col0 + tx * 8;
            float v[8];
#pragma unroll
            for (int j = 0; j < 8; ++j) {
                float t = acc[i][j] + bb[j];
                t = (t > 0.f) ? t : 0.01f * t;
                v[j] = t;
                __nv_bfloat16 hv = __float2bfloat16(t);
                ohi[ob + j] = hv;
                olo[ob + j] = __float2bfloat16(t - __bfloat162float(hv));
            }
            *(float4*)(Cout + ob)     = make_float4(v[0], v[1], v[2], v[3]);
            *(float4*)(Cout + ob + 4) = make_float4(v[4], v[5], v[6], v[7]);
        }
    }
}

// ---------------- helpers for agg ---------------------------------------------
__device__ __forceinline__ void ld8(float* d, const float* p) {
    float4 a = *(const float4*)p;
    float4 b = *(const float4*)(p + 4);
    d[0]=a.x; d[1]=a.y; d[2]=a.z; d[3]=a.w;
    d[4]=b.x; d[5]=b.y; d[6]=b.z; d[7]=b.w;
}

// ---------------- GATv2 agg, warp-per-head (H=4), edge-pair ILP ---------------
__global__ __launch_bounds__(128) void gat_agg_w(
    const float* __restrict__ xl, const float* __restrict__ xr,
    const float* __restrict__ att, const float* __restrict__ bias,
    __nv_bfloat16* __restrict__ ohi, __nv_bfloat16* __restrict__ olo) {
    int node = blockIdx.x;
    int w    = threadIdx.x >> 5;
    int lane = threadIdx.x & 31;
    int cof  = w * CCH + lane * 8;               // channel offset in [H*C]
    size_t ib = (size_t)node * HCD + cof;

    float attv[8], xrv[8], acc[8];
#pragma unroll
    for (int j = 0; j < 8; ++j) { attv[j] = att[cof + j]; acc[j] = 0.f; }
    ld8(xrv, xr + ib);

    int pbeg = g_off[node], pend = g_off[node + 1];
    float m = -INFINITY, den = 0.f;

    float cur0[8], cur1[8];
    ld8(cur0, xl + (size_t)g_csr[pbeg] * HCD + cof);
    if (pbeg + 1 < pend)
        ld8(cur1, xl + (size_t)g_csr[pbeg + 1] * HCD + cof);

    int p = pbeg;
    while (p + 1 < pend) {
        float nxt0[8], nxt1[8];
        bool n0 = (p + 2 < pend), n1 = (p + 3 < pend);
        if (n0) ld8(nxt0, xl + (size_t)g_csr[p + 2] * HCD + cof);
        if (n1) ld8(nxt1, xl + (size_t)g_csr[p + 3] * HCD + cof);
        float p0 = 0.f, p1 = 0.f;
#pragma unroll
        for (int j = 0; j < 8; ++j) {
            float t0 = cur0[j] + xrv[j];
            t0 = (t0 > 0.f) ? t0 : 0.2f * t0;
            p0 = fmaf(attv[j], t0, p0);
            float t1 = cur1[j] + xrv[j];
            t1 = (t1 > 0.f) ? t1 : 0.2f * t1;
            p1 = fmaf(attv[j], t1, p1);
        }
#pragma unroll
        for (int o = 16; o > 0; o >>= 1) {
            p0 += __shfl_xor_sync(0xffffffffu, p0, o);
            p1 += __shfl_xor_sync(0xffffffffu, p1, o);
        }
        float nm = fmaxf(m, fmaxf(p0, p1));
        float sc = __expf(m - nm);
        float e0 = __expf(p0 - nm);
        float e1 = __expf(p1 - nm);
        den = den * sc + e0 + e1;
#pragma unroll
        for (int j = 0; j < 8; ++j)
            acc[j] = fmaf(acc[j], sc, fmaf(e0, cur0[j], e1 * cur1[j]));
        m = nm;
        if (n0) {
#pragma unroll
            for (int j = 0; j < 8; ++j) cur0[j] = nxt0[j];
        }
        if (n1) {
#pragma unroll
            for (int j = 0; j < 8; ++j) cur1[j] = nxt1[j];
        }
        p += 2;
    }
    if (p < pend) {       // odd tail (cur0 holds edge p)
        float p0 = 0.f;
#pragma unroll
        for (int j = 0; j < 8; ++j) {
            float t0 = cur0[j] + xrv[j];
            t0 = (t0 > 0.f) ? t0 : 0.2f * t0;
            p0 = fmaf(attv[j], t0, p0);
        }
#pragma unroll
        for (int o = 16; o > 0; o >>= 1)
            p0 += __shfl_xor_sync(0xffffffffu, p0, o);
        float nm = fmaxf(m, p0);
        float sc = __expf(m - nm);
        float e0 = __expf(p0 - nm);
        den = den * sc + e0;
#pragma unroll
        for (int j = 0; j < 8; ++j) acc[j] = fmaf(acc[j], sc, e0 * cur0[j]);
    }

    float inv = 1.f / den;
#pragma unroll
    for (int j = 0; j < 8; ++j) {
        float v = acc[j] * inv + bias[cof + j];
        v = (v > 0.f) ? v : expm1f(v);           // elu
        __nv_bfloat16 hv = __float2bfloat16(v);
        ohi[ib + j] = hv;
        olo[ib + j] = __float2bfloat16(v - __bfloat162float(hv));
    }
}

// ---------------- conv3 agg (H=1) fused with output layer ---------------------
__global__ __launch_bounds__(256) void gat_final(
    const float* __restrict__ xl, const float* __restrict__ xr,
    const float* __restrict__ att, const float* __restrict__ bias,
    const float* __restrict__ Wout, const float* __restrict__ bout,
    float* __restrict__ outp) {
    int node = blockIdx.x * 8 + (threadIdx.x >> 5);
    if (node >= NN) return;
    int lane = threadIdx.x & 31;
    int cof  = lane * 8;
    size_t ib = (size_t)node * CCH + cof;

    float attv[8], xrv[8], acc[8];
#pragma unroll
    for (int j = 0; j < 8; ++j) { attv[j] = att[cof + j]; acc[j] = 0.f; }
    ld8(xrv, xr + ib);

    int pbeg = g_off[node], pend = g_off[node + 1];
    float m = -INFINITY, den = 0.f;

    float cur0[8], cur1[8];
    ld8(cur0, xl + (size_t)g_csr[pbeg] * CCH + cof);
    if (pbeg + 1 < pend)
        ld8(cur1, xl + (size_t)g_csr[pbeg + 1] * CCH + cof);

    int p = pbeg;
    while (p + 1 < pend) {
        float nxt0[8], nxt1[8];
        bool n0 = (p + 2 < pend), n1 = (p + 3 < pend);
        if (n0) ld8(nxt0, xl + (size_t)g_csr[p + 2] * CCH + cof);
        if (n1) ld8(nxt1, xl + (size_t)g_csr[p + 3] * CCH + cof);
        float p0 = 0.f, p1 = 0.f;
#pragma unroll
        for (int j = 0; j < 8; ++j) {
            float t0 = cur0[j] + xrv[j];
            t0 = (t0 > 0.f) ? t0 : 0.2f * t0;
            p0 = fmaf(attv[j], t0, p0);
            float t1 = cur1[j] + xrv[j];
            t1 = (t1 > 0.f) ? t1 : 0.2f * t1;
            p1 = fmaf(attv[j], t1, p1);
        }
#pragma unroll
        for (int o = 16; o > 0; o >>= 1) {
            p0 += __shfl_xor_sync(0xffffffffu, p0, o);
            p1 += __shfl_xor_sync(0xffffffffu, p1, o);
        }
        float nm = fmaxf(m, fmaxf(p0, p1));
        float sc = __expf(m - nm);
        float e0 = __expf(p0 - nm);
        float e1 = __expf(p1 - nm);
        den = den * sc + e0 + e1;
#pragma unroll
        for (int j = 0; j < 8; ++j)
            acc[j] = fmaf(acc[j], sc, fmaf(e0, cur0[j], e1 * cur1[j]));
        m = nm;
        if (n0) {
#pragma unroll
            for (int j = 0; j < 8; ++j) cur0[j] = nxt0[j];
        }
        if (n1) {
#pragma unroll
            for (int j = 0; j < 8; ++j) cur1[j] = nxt1[j];
        }
        p += 2;
    }
    if (p < pend) {
        float p0 = 0.f;
#pragma unroll
        for (int j = 0; j < 8; ++j) {
            float t0 = cur0[j] + xrv[j];
            t0 = (t0 > 0.f) ? t0 : 0.2f * t0;
            p0 = fmaf(attv[j], t0, p0);
        }
#pragma unroll
        for (int o = 16; o > 0; o >>= 1)
            p0 += __shfl_xor_sync(0xffffffffu, p0, o);
        float nm = fmaxf(m, p0);
        float sc = __expf(m - nm);
        float e0 = __expf(p0 - nm);
        den = den * sc + e0;
#pragma unroll
        for (int j = 0; j < 8; ++j) acc[j] = fmaf(acc[j], sc, e0 * cur0[j]);
    }

    float inv = 1.f / den;
    float sum = 0.f;
#pragma unroll
    for (int j = 0; j < 8; ++j) {
        float v = acc[j] * inv + bias[cof + j];
        v = (v > 0.f) ? v : 0.01f * v;           // leaky
        v += g_h[ib + j];                        // residual
        sum = fmaf(v, Wout[cof + j], sum);
    }
#pragma unroll
    for (int o = 16; o > 0; o >>= 1)
        sum += __shfl_xor_sync(0xffffffffu, sum, o);
    if (lane == 0) outp[node] = sum + bout[0];
}

// ---------------- launch ------------------------------------------------------
extern "C" void kernel_launch(void* const* d_in, const int* in_sizes, int n_in,
                              void* d_out, int out_size) {
    const float* x    = (const float*)d_in[0];
    const int*   src  = (const int*)  d_in[1];
    const int*   dst  = (const int*)  d_in[2];
    const float* W_in = (const float*)d_in[3];
    const float* b_in = (const float*)d_in[4];
    const float* Wl1  = (const float*)d_in[5];
    const float* bl1  = (const float*)d_in[6];
    const float* Wr1  = (const float*)d_in[7];
    const float* br1  = (const float*)d_in[8];
    const float* att1 = (const float*)d_in[9];
    const float* bias1= (const float*)d_in[10];
    const float* Wl2  = (const float*)d_in[11];
    const float* bl2  = (const float*)d_in[12];
    const float* Wr2  = (const float*)d_in[13];
    const float* br2  = (const float*)d_in[14];
    const float* att2 = (const float*)d_in[15];
    const float* bias2= (const float*)d_in[16];
    const float* Wl3  = (const float*)d_in[17];
    const float* bl3  = (const float*)d_in[18];
    const float* Wr3  = (const float*)d_in[19];
    const float* br3  = (const float*)d_in[20];
    const float* att3 = (const float*)d_in[21];
    const float* bias3= (const float*)d_in[22];
    const float* Wout = (const float*)d_in[23];
    const float* bout = (const float*)d_in[24];
    float* outp = (float*)d_out;

    float *h, *xl, *xr;
    __nv_bfloat16 *ahi, *alo, *w1h, *w1l, *w2h, *w2l, *w3h, *w3l;
    cudaGetSymbolAddress((void**)&h,  g_h);
    cudaGetSymbolAddress((void**)&xl, g_xl);
    cudaGetSymbolAddress((void**)&xr, g_xr);
    cudaGetSymbolAddress((void**)&ahi, g_ahi);
    cudaGetSymbolAddress((void**)&alo, g_alo);
    cudaGetSymbolAddress((void**)&w1h, g_w1hi);
    cudaGetSymbolAddress((void**)&w1l, g_w1lo);
    cudaGetSymbolAddress((void**)&w2h, g_w2hi);
    cudaGetSymbolAddress((void**)&w2l, g_w2lo);
    cudaGetSymbolAddress((void**)&w3h, g_w3hi);
    cudaGetSymbolAddress((void**)&w3l, g_w3lo);

    cudaFuncSetAttribute(gemm_b3, cudaFuncAttributeMaxDynamicSharedMemorySize, GEMM_SMEM);

    dim3 blk(256);
    int mgrid = (NN + 127) / 128;

    // fork a side stream off the capturing (default) stream
    cudaStream_t s2;
    cudaStreamCreateWithFlags(&s2, cudaStreamNonBlocking);
    cudaEvent_t evFork, evJoin;
    cudaEventCreateWithFlags(&evFork, cudaEventDisableTiming);
    cudaEventCreateWithFlags(&evJoin, cudaEventDisableTiming);

    cudaEventRecord(evFork, 0);
    cudaStreamWaitEvent(s2, evFork, 0);

    // side stream: CSR build + conv2/conv3 weight splits (independent of mainline)
    k_zero_deg<<<(NN + 255) / 256, 256, 0, s2>>>();
    k_count<<<(ET + 255) / 256, 256, 0, s2>>>(dst);
    k_scan<<<1, 1024, 0, s2>>>();
    k_fill<<<(ET + 255) / 256, 256, 0, s2>>>(src, dst);
    k_splitT<<<dim3(1024 / 32, 1024 / 32), blk, 0, s2>>>(Wl2, w2h, w2l, 1024, 1024, 0);
    k_splitT<<<dim3(1024 / 32, 1024 / 32), blk, 0, s2>>>(Wr2, w2h, w2l, 1024, 1024, 1024);
    k_splitT<<<dim3(256 / 32, 1024 / 32), blk, 0, s2>>>(Wl3, w3h, w3l, 1024, 256, 0);
    k_splitT<<<dim3(256 / 32, 1024 / 32), blk, 0, s2>>>(Wr3, w3h, w3l, 1024, 256, 256);
    cudaEventRecord(evJoin, s2);

    // main stream: input layer + conv1 weights + gemm1
    sgemm_in<<<dim3(2, mgrid), blk>>>(x, W_in, b_in, h, ahi, alo, NN, 256, DINV);
    k_splitT<<<dim3(1024 / 32, 256 / 32), blk>>>(Wl1, w1h, w1l, 256, 1024, 0);
    k_splitT<<<dim3(1024 / 32, 256 / 32), blk>>>(Wr1, w1h, w1l, 256, 1024, 1024);
    gemm_b3<<<dim3(16, mgrid), blk, GEMM_SMEM>>>(ahi, alo, w1h, w1l, bl1, br1,
                                                 xl, xr, NN, 1024, 1024, 256);

    // join: agg1 needs CSR; gemm2 needs w2
    cudaStreamWaitEvent(0, evJoin, 0);

    gat_agg_w<<<NN, 128>>>(xl, xr, att1, bias1, ahi, alo);

    gemm_b3<<<dim3(16, mgrid), blk, GEMM_SMEM>>>(ahi, alo, w2h, w2l, bl2, br2,
                                                 xl, xr, NN, 1024, 1024, 1024);
    gat_agg_w<<<NN, 128>>>(xl, xr, att2, bias2, ahi, alo);

    gemm_b3<<<dim3(4, mgrid), blk, GEMM_SMEM>>>(ahi, alo, w3h, w3l, bl3, br3,
                                                xl, xr, NN, 256, 256, 1024);
    gat_final<<<(NN + 7) / 8, 256>>>(xl, xr, att3, bias3, Wout, bout, outp);

    cudaStreamDestroy(s2);
    cudaEventDestroy(evFork);
    cudaEventDestroy(evJoin);
}